// round 10
// baseline (speedup 1.0000x reference)
#include <cuda_runtime.h>
#include <cuda_fp16.h>
#include <math.h>
#include <stdint.h>

#define BB   4
#define SS   2048
#define DD   1024
#define NH   16
#define NKV  4
#define DK   64

// -------- scratch (no allocations allowed) --------
__device__ uint4 g_q[BB * SS * NH * DK / 8];
__device__ uint4 g_k[BB * SS * NKV * DK / 8];
__device__ uint4 g_v[BB * SS * NKV * DK / 8];
__device__ uint4 g_ctx[BB * SS * DD / 8];
__device__ uint4 g_xh[BB * SS * DD / 8];          // x in half
__device__ uint4 g_wqkvT[1536 * 1024 / 8];        // [Wq|Wk|Wv]^T half, [N,K]
__device__ uint4 g_woT[1024 * 1024 / 8];          // Wo^T half, [N,K]
__device__ float g_cosT[SS * 32];                 // rope tables
__device__ float g_sinT[SS * 32];

__device__ __forceinline__ uint32_t h2(float a, float b) {
    __half2 h = __floats2half2_rn(a, b);
    return *(uint32_t*)&h;
}
__device__ __forceinline__ void mma_f16(float c[4],
    uint32_t a0, uint32_t a1, uint32_t a2, uint32_t a3,
    uint32_t b0, uint32_t b1)
{
    asm volatile(
        "mma.sync.aligned.m16n8k16.row.col.f32.f16.f16.f32 "
        "{%0,%1,%2,%3}, {%4,%5,%6,%7}, {%8,%9}, {%0,%1,%2,%3};\n"
        : "+f"(c[0]), "+f"(c[1]), "+f"(c[2]), "+f"(c[3])
        : "r"(a0), "r"(a1), "r"(a2), "r"(a3), "r"(b0), "r"(b1));
}
__device__ __forceinline__ void ldsm4(uint32_t d[4], uint32_t saddr) {
    asm volatile("ldmatrix.sync.aligned.m8n8.x4.shared.b16 {%0,%1,%2,%3}, [%4];\n"
        : "=r"(d[0]), "=r"(d[1]), "=r"(d[2]), "=r"(d[3]) : "r"(saddr));
}
__device__ __forceinline__ void ldsm4t(uint32_t d[4], uint32_t saddr) {
    asm volatile("ldmatrix.sync.aligned.m8n8.x4.trans.shared.b16 {%0,%1,%2,%3}, [%4];\n"
        : "=r"(d[0]), "=r"(d[1]), "=r"(d[2]), "=r"(d[3]) : "r"(saddr));
}
#define CP16(dst, src) \
    asm volatile("cp.async.cg.shared.global [%0], [%1], 16;\n" :: "r"(dst), "l"(src))
#define CP_COMMIT()  asm volatile("cp.async.commit_group;\n" ::)
#define CP_WAIT0()   asm volatile("cp.async.wait_group 0;\n" ::)
#define CP_WAIT1()   asm volatile("cp.async.wait_group 1;\n" ::)

// ============================================================
// helpers: convert x, build rope tables, transpose weights
// ============================================================
__global__ void convert_x(const float4* __restrict__ x, uint2* __restrict__ xh, int n4)
{
    int i = blockIdx.x * blockDim.x + threadIdx.x;
    if (i >= n4) return;
    float4 t = x[i];
    xh[i] = make_uint2(h2(t.x, t.y), h2(t.z, t.w));
}

__global__ void build_cs()
{
    int i = blockIdx.x * blockDim.x + threadIdx.x;
    if (i >= SS * 32) return;
    int s = i >> 5, f = i & 31;
    float theta = powf(10000.0f, -(float)f / 32.0f);
    float sn, cs;
    sincosf((float)s * theta, &sn, &cs);
    g_cosT[i] = cs;
    g_sinT[i] = sn;
}

__global__ void transpose_w(const float* __restrict__ Wq, const float* __restrict__ Wk,
                            const float* __restrict__ Wv, const float* __restrict__ Wo,
                            __half* __restrict__ wqkvT, __half* __restrict__ woT)
{
    __shared__ float tile[32][33];
    const int z = blockIdx.z;
    const float* src; __half* dst; int C;
    if      (z == 0) { src = Wq; dst = wqkvT;               C = 1024; }
    else if (z == 1) { src = Wk; dst = wqkvT + 1024 * 1024; C = 256;  }
    else if (z == 2) { src = Wv; dst = wqkvT + 1280 * 1024; C = 256;  }
    else             { src = Wo; dst = woT;                 C = 1024; }

    int c0 = blockIdx.x * 32;
    if (c0 >= C) return;
    int r0 = blockIdx.y * 32;
    int tx = threadIdx.x, ty = threadIdx.y;

#pragma unroll
    for (int i = 0; i < 4; i++)
        tile[ty + i * 8][tx] = src[(size_t)(r0 + ty + i * 8) * C + c0 + tx];
    __syncthreads();
#pragma unroll
    for (int i = 0; i < 4; i++)
        dst[(size_t)(c0 + ty + i * 8) * 1024 + r0 + tx] =
            __float2half_rn(tile[tx][ty + i * 8]);
}

// ============================================================
// All-half GEMM: C[M,N] = A[M,K] @ Bt[N,K]^T
// 128x128 tiles, 64-K stages, double-buffered cp.async,
// 256 threads (8 warps, warp tile 32x64), ldmatrix fragments.
// MODE 0: half qkv output + fused RoPE. MODE 1: float out.
// ============================================================
#define GSTR 36                       // word stride per 64-half row (+4 pad)
#define G_AW (128 * GSTR)             // A words per stage
#define G_SW (2 * G_AW)               // stage words (A + B)
#define GEMM_SMEM (2 * G_SW * 4)      // 73728 B

template<int MODE>
__global__ __launch_bounds__(256, 2) void gemm_h(
    const uint4* __restrict__ A4, const uint4* __restrict__ B4,
    uint32_t* __restrict__ qp, uint32_t* __restrict__ kp, uint32_t* __restrict__ vp,
    float* __restrict__ outp, int K, int KT)
{
    extern __shared__ __align__(16) uint32_t gsm[];
    const uint32_t smA = (uint32_t)__cvta_generic_to_shared(gsm);

    const int tid  = threadIdx.x;
    const int warp = tid >> 5;
    const int lane = tid & 31;
    const int lr   = lane >> 2;
    const int lc   = lane & 3;
    const int g    = lane >> 3;
    const int r8   = lane & 7;
    const int gh   = g & 1;
    const int gv   = g >> 1;
    const int wrow = (warp & 3) * 32;
    const int wcol = (warp >> 2) * 64;
    const long rowBase = (long)blockIdx.y * 128;
    const long colBase = (long)blockIdx.x * 128;

    // loader: threads 0-127 -> A rows, 128-255 -> B rows; 128B (8 chunks)/thread/stage
    const int  lrow = tid & 127;
    const bool isB  = (tid >= 128);
    const uint4* srcRow = isB
        ? B4 + (size_t)(colBase + lrow) * (K >> 3)
        : A4 + (size_t)(rowBase + lrow) * (K >> 3);
    const uint32_t dstw = (isB ? G_AW : 0) + lrow * GSTR;

    auto stage = [&](int c) {
        uint32_t base = smA + ((c & 1) * G_SW + dstw) * 4;
#pragma unroll
        for (int ch = 0; ch < 8; ch++)
            CP16(base + ch * 16, srcRow + c * 8 + ch);
        CP_COMMIT();
    };

    float acc[2][8][4];
#pragma unroll
    for (int i = 0; i < 2; i++)
#pragma unroll
        for (int j = 0; j < 8; j++)
#pragma unroll
            for (int r = 0; r < 4; r++) acc[i][j][r] = 0.0f;

    stage(0);

    for (int kt = 0; kt < KT; kt++) {
        __syncthreads();                  // all warps done reading buffer (kt+1)&1
        if (kt + 1 < KT) { stage(kt + 1); CP_WAIT1(); }
        else CP_WAIT0();
        __syncthreads();                  // stage kt visible to all

        const uint32_t curA = smA + (kt & 1) * G_SW * 4;
        const uint32_t curB = curA + G_AW * 4;

#pragma unroll
        for (int kc = 0; kc < 4; kc++) {
            uint32_t af[2][4];
#pragma unroll
            for (int ma = 0; ma < 2; ma++)
                ldsm4(af[ma], curA + ((wrow + ma * 16 + gh * 8 + r8) * GSTR + kc * 8 + gv * 4) * 4);
#pragma unroll
            for (int na2 = 0; na2 < 4; na2++) {
                uint32_t bd[4];
                ldsm4(bd, curB + ((wcol + na2 * 16 + gv * 8 + r8) * GSTR + kc * 8 + gh * 4) * 4);
#pragma unroll
                for (int ma = 0; ma < 2; ma++) {
                    mma_f16(acc[ma][2 * na2],     af[ma][0], af[ma][1], af[ma][2], af[ma][3], bd[0], bd[1]);
                    mma_f16(acc[ma][2 * na2 + 1], af[ma][0], af[ma][1], af[ma][2], af[ma][3], bd[2], bd[3]);
                }
            }
        }
    }

    // epilogue
    if (MODE == 0) {
        uint32_t* T; int tstride, toff;
        if (colBase < 1024)      { T = qp; tstride = 1024; toff = (int)colBase; }
        else if (colBase < 1280) { T = kp; tstride = 256;  toff = (int)colBase - 1024; }
        else                     { T = vp; tstride = 256;  toff = (int)colBase - 1280; }
        const bool  doRope = (colBase < 1280);
        const float qscale = (colBase < 1024) ? 0.125f : 1.0f;

#pragma unroll
        for (int ma = 0; ma < 2; ma++) {
            long r0 = rowBase + wrow + ma * 16 + lr;
            if (doRope) {
                int s0 = (int)(r0 & (SS - 1));
                int s1 = (int)((r0 + 8) & (SS - 1));
#pragma unroll
                for (int na = 0; na < 4; na++) {
                    int f = na * 8 + 2 * lc;
                    float2 c0 = *(const float2*)(g_cosT + s0 * 32 + f);
                    float2 n0 = *(const float2*)(g_sinT + s0 * 32 + f);
                    float2 c1 = *(const float2*)(g_cosT + s1 * 32 + f);
                    float2 n1 = *(const float2*)(g_sinT + s1 * 32 + f);
                    float x0 = acc[ma][na][0], x1 = acc[ma][na][1];
                    float y0 = acc[ma][na + 4][0], y1 = acc[ma][na + 4][1];
                    acc[ma][na][0]     = x0 * c0.x - y0 * n0.x;
                    acc[ma][na + 4][0] = y0 * c0.x + x0 * n0.x;
                    acc[ma][na][1]     = x1 * c0.y - y1 * n0.y;
                    acc[ma][na + 4][1] = y1 * c0.y + x1 * n0.y;
                    float x2 = acc[ma][na][2], x3 = acc[ma][na][3];
                    float y2 = acc[ma][na + 4][2], y3 = acc[ma][na + 4][3];
                    acc[ma][na][2]     = x2 * c1.x - y2 * n1.x;
                    acc[ma][na + 4][2] = y2 * c1.x + x2 * n1.x;
                    acc[ma][na][3]     = x3 * c1.y - y3 * n1.y;
                    acc[ma][na + 4][3] = y3 * c1.y + x3 * n1.y;
                }
            }
#pragma unroll
            for (int na = 0; na < 8; na++) {
                int col = toff + wcol + na * 8 + 2 * lc;
                T[(r0 * tstride + col) >> 1] =
                    h2(acc[ma][na][0] * qscale, acc[ma][na][1] * qscale);
                T[((r0 + 8) * tstride + col) >> 1] =
                    h2(acc[ma][na][2] * qscale, acc[ma][na][3] * qscale);
            }
        }
    } else {
#pragma unroll
        for (int ma = 0; ma < 2; ma++) {
            long r0 = rowBase + wrow + ma * 16 + lr;
#pragma unroll
            for (int na = 0; na < 8; na++) {
                int col = (int)colBase + wcol + na * 8 + 2 * lc;
                *(float2*)(outp + r0 * DD + col) =
                    make_float2(acc[ma][na][0], acc[ma][na][1]);
                *(float2*)(outp + (r0 + 8) * DD + col) =
                    make_float2(acc[ma][na][2], acc[ma][na][3]);
            }
        }
    }
}

// ============================================================
// FP16 flash attention: 128-q tiles, 256 threads (8 warps x 16 rows),
// 64-key tiles, cp.async triple-buffered KV, ONE sync per tile.
// ============================================================
#define FSTR 36
#define FLASH_SMEM ((128 + 128 + 3 * 128) * FSTR * 4)

__global__ __launch_bounds__(256) void flash_f16(
    const uint4* __restrict__ Q, const uint4* __restrict__ K,
    const uint4* __restrict__ V, uint32_t* __restrict__ O)
{
    extern __shared__ __align__(16) uint32_t fsm[];
    uint32_t* sQ  = fsm;
    uint32_t* sP  = sQ + 128 * FSTR;
    uint32_t* sKV = sP + 128 * FSTR;

    const int tid  = threadIdx.x;
    const int warp = tid >> 5;
    const int lane = tid & 31;
    const int lr   = lane >> 2;
    const int lc   = lane & 3;
    const int g    = lane >> 3;
    const int r8   = lane & 7;
    const int gh   = g & 1;
    const int gv   = g >> 1;
    const int qt   = gridDim.x - 1 - blockIdx.x;
    const int qb   = qt * 128;
    const int h    = blockIdx.y;
    const int b    = blockIdx.z;
    const int kvh  = h >> 2;
    const int ntiles = 2 * qt + 2;

    const uint32_t sQa  = (uint32_t)__cvta_generic_to_shared(sQ);
    const uint32_t sPa  = (uint32_t)__cvta_generic_to_shared(sP);
    const uint32_t sKVa = (uint32_t)__cvta_generic_to_shared(sKV);

    const int si = tid;
    auto stageKV = [&](int kt, int buf) {
        uint32_t bufa = sKVa + buf * 128 * FSTR * 4;
#pragma unroll
        for (int u = 0; u < 4; u++) {
            int i   = si + u * 256;
            int idx = i & 511;
            int r   = idx >> 3, c = idx & 7;
            const uint4* src = ((i < 512) ? K : V) +
                ((size_t)(b * SS + kt * 64 + r) * NKV + kvh) * 8 + c;
            uint32_t dst = bufa + (((i < 512) ? 0 : 64 * FSTR) + r * FSTR + c * 4) * 4;
            CP16(dst, src);
        }
        CP_COMMIT();
    };

    for (int i = tid; i < 1024; i += 256) {
        int r = i >> 3, c = i & 7;
        *(uint4*)&sQ[r * FSTR + c * 4] = Q[((size_t)(b * SS + qb + r) * NH + h) * 8 + c];
    }

    stageKV(0, 0);
    stageKV(1, 1);

    float acc[8][4];
#pragma unroll
    for (int na = 0; na < 8; na++)
#pragma unroll
        for (int r = 0; r < 4; r++) acc[na][r] = 0.0f;
    float m_lo = -1e30f, m_hi = -1e30f, l_lo = 0.0f, l_hi = 0.0f;

    uint32_t* pw = sP + warp * 16 * FSTR;
    const uint32_t pwa = sPa + warp * 16 * FSTR * 4;
    const int wr_lo = warp * 16;
    uint32_t qf[4][4];
    bool qloaded = false;

    for (int kt = 0; kt < ntiles; kt++) {
        if (kt + 1 < ntiles) CP_WAIT1(); else CP_WAIT0();
        __syncthreads();
        if (kt + 2 < ntiles) stageKV(kt + 2, (kt + 2) % 3);

        if (!qloaded) {
            qloaded = true;
#pragma unroll
            for (int kc = 0; kc < 4; kc++)
                ldsm4(qf[kc], sQa + ((warp * 16 + gh * 8 + r8) * FSTR + kc * 8 + gv * 4) * 4);
        }

        const uint32_t cura = sKVa + (kt % 3) * 128 * FSTR * 4;
        const uint32_t curK = cura;
        const uint32_t curV = cura + 64 * FSTR * 4;

        const int relq = qb + wr_lo - kt * 64;
        if (relq + 15 >= 0) {
            float sc[8][4];
#pragma unroll
            for (int na = 0; na < 8; na++)
                sc[na][0] = sc[na][1] = sc[na][2] = sc[na][3] = 0.0f;
#pragma unroll
            for (int na2 = 0; na2 < 4; na2++) {
#pragma unroll
                for (int kc = 0; kc < 4; kc++) {
                    uint32_t kd[4];
                    ldsm4(kd, curK + ((na2 * 16 + gv * 8 + r8) * FSTR + kc * 8 + gh * 4) * 4);
                    mma_f16(sc[2*na2],     qf[kc][0], qf[kc][1], qf[kc][2], qf[kc][3], kd[0], kd[1]);
                    mma_f16(sc[2*na2 + 1], qf[kc][0], qf[kc][1], qf[kc][2], qf[kc][3], kd[2], kd[3]);
                }
            }

            if (relq < 63) {
#pragma unroll
                for (int na = 0; na < 8; na++) {
                    int col = na * 8 + 2 * lc;
                    if (col     > relq + lr)     sc[na][0] = -1e30f;
                    if (col + 1 > relq + lr)     sc[na][1] = -1e30f;
                    if (col     > relq + lr + 8) sc[na][2] = -1e30f;
                    if (col + 1 > relq + lr + 8) sc[na][3] = -1e30f;
                }
            }

            float rm_lo = -1e30f, rm_hi = -1e30f;
#pragma unroll
            for (int na = 0; na < 8; na++) {
                rm_lo = fmaxf(rm_lo, fmaxf(sc[na][0], sc[na][1]));
                rm_hi = fmaxf(rm_hi, fmaxf(sc[na][2], sc[na][3]));
            }
            rm_lo = fmaxf(rm_lo, __shfl_xor_sync(0xffffffff, rm_lo, 1));
            rm_lo = fmaxf(rm_lo, __shfl_xor_sync(0xffffffff, rm_lo, 2));
            rm_hi = fmaxf(rm_hi, __shfl_xor_sync(0xffffffff, rm_hi, 1));
            rm_hi = fmaxf(rm_hi, __shfl_xor_sync(0xffffffff, rm_hi, 2));

            float mn_lo = fmaxf(m_lo, rm_lo);
            float mn_hi = fmaxf(m_hi, rm_hi);
            float corr_lo = __expf(m_lo - mn_lo);
            float corr_hi = __expf(m_hi - mn_hi);
            m_lo = mn_lo; m_hi = mn_hi;

            float ps_lo = 0.0f, ps_hi = 0.0f;
#pragma unroll
            for (int na = 0; na < 8; na++) {
                float p0 = __expf(sc[na][0] - m_lo);
                float p1 = __expf(sc[na][1] - m_lo);
                float p2 = __expf(sc[na][2] - m_hi);
                float p3 = __expf(sc[na][3] - m_hi);
                ps_lo += p0 + p1;
                ps_hi += p2 + p3;
                pw[lr * FSTR + na * 4 + lc]       = h2(p0, p1);
                pw[(lr + 8) * FSTR + na * 4 + lc] = h2(p2, p3);
                acc[na][0] *= corr_lo; acc[na][1] *= corr_lo;
                acc[na][2] *= corr_hi; acc[na][3] *= corr_hi;
            }
            ps_lo += __shfl_xor_sync(0xffffffff, ps_lo, 1);
            ps_lo += __shfl_xor_sync(0xffffffff, ps_lo, 2);
            ps_hi += __shfl_xor_sync(0xffffffff, ps_hi, 1);
            ps_hi += __shfl_xor_sync(0xffffffff, ps_hi, 2);
            l_lo = l_lo * corr_lo + ps_lo;
            l_hi = l_hi * corr_hi + ps_hi;

            __syncwarp();

#pragma unroll
            for (int kc = 0; kc < 4; kc++) {
                uint32_t pf[4];
                ldsm4(pf, pwa + ((gh * 8 + r8) * FSTR + kc * 8 + gv * 4) * 4);
#pragma unroll
                for (int na2 = 0; na2 < 4; na2++) {
                    uint32_t vd[4];
                    ldsm4t(vd, curV + ((kc * 16 + gh * 8 + r8) * FSTR + na2 * 8 + gv * 4) * 4);
                    mma_f16(acc[2*na2],     pf[0], pf[1], pf[2], pf[3], vd[0], vd[1]);
                    mma_f16(acc[2*na2 + 1], pf[0], pf[1], pf[2], pf[3], vd[2], vd[3]);
                }
            }
        }
    }

    float inv_lo = 1.0f / l_lo;
    float inv_hi = 1.0f / l_hi;
    size_t r0 = (size_t)(b * SS + qb + warp * 16 + lr);
    size_t r1 = r0 + 8;
#pragma unroll
    for (int na = 0; na < 8; na++) {
        int wd = na * 4 + lc;
        O[(r0 * NH + h) * 32 + wd] = h2(acc[na][0] * inv_lo, acc[na][1] * inv_lo);
        O[(r1 * NH + h) * 32 + wd] = h2(acc[na][2] * inv_hi, acc[na][3] * inv_hi);
    }
}

// ============================================================
// launch
// ============================================================
extern "C" void kernel_launch(void* const* d_in, const int* in_sizes, int n_in,
                              void* d_out, int out_size)
{
    const float* x  = (const float*)d_in[0];
    const float* Wq = (const float*)d_in[1];
    const float* Wk = (const float*)d_in[2];
    const float* Wv = (const float*)d_in[3];
    const float* Wo = (const float*)d_in[4];
    float* out = (float*)d_out;

    void *q, *k, *v, *ctx, *xh, *wqkvT, *woT;
    cudaGetSymbolAddress(&q,     g_q);
    cudaGetSymbolAddress(&k,     g_k);
    cudaGetSymbolAddress(&v,     g_v);
    cudaGetSymbolAddress(&ctx,   g_ctx);
    cudaGetSymbolAddress(&xh,    g_xh);
    cudaGetSymbolAddress(&wqkvT, g_wqkvT);
    cudaGetSymbolAddress(&woT,   g_woT);

    const int M = BB * SS;  // 8192

    cudaFuncSetAttribute(gemm_h<0>, cudaFuncAttributeMaxDynamicSharedMemorySize, GEMM_SMEM);
    cudaFuncSetAttribute(gemm_h<1>, cudaFuncAttributeMaxDynamicSharedMemorySize, GEMM_SMEM);
    cudaFuncSetAttribute(flash_f16, cudaFuncAttributeMaxDynamicSharedMemorySize, FLASH_SMEM);

    convert_x<<<(M * DD / 4 + 255) / 256, 256>>>(
        (const float4*)x, (uint2*)xh, M * DD / 4);
    build_cs<<<(SS * 32 + 255) / 256, 256>>>();
    transpose_w<<<dim3(32, 32, 4), dim3(32, 8)>>>(
        Wq, Wk, Wv, Wo, (__half*)wqkvT, (__half*)woT);

    // fused QKV projection + RoPE
    gemm_h<0><<<dim3(12, M / 128), 256, GEMM_SMEM>>>(
        (const uint4*)xh, (const uint4*)wqkvT,
        (uint32_t*)q, (uint32_t*)k, (uint32_t*)v, nullptr, DD, DD / 64);

    // attention
    flash_f16<<<dim3(SS / 128, NH, BB), 256, FLASH_SMEM>>>(
        (const uint4*)q, (const uint4*)k, (const uint4*)v, (uint32_t*)ctx);

    // output projection
    gemm_h<1><<<dim3(8, M / 128), 256, GEMM_SMEM>>>(
        (const uint4*)ctx, (const uint4*)woT,
        nullptr, nullptr, nullptr, out, DD, DD / 64);
}

// round 11
// speedup vs baseline: 1.0530x; 1.0530x over previous
#include <cuda_runtime.h>
#include <cuda_fp16.h>
#include <math.h>
#include <stdint.h>

#define BB   4
#define SS   2048
#define DD   1024
#define NH   16
#define NKV  4
#define DK   64

// -------- scratch (no allocations allowed) --------
__device__ uint4 g_q[BB * SS * NH * DK / 8];
__device__ uint4 g_k[BB * SS * NKV * DK / 8];
__device__ uint4 g_v[BB * SS * NKV * DK / 8];
__device__ uint4 g_ctx[BB * SS * DD / 8];
__device__ uint4 g_xh[BB * SS * DD / 8];          // x in half
__device__ uint4 g_wqkvT[1536 * 1024 / 8];        // [Wq|Wk|Wv]^T half, [N,K]
__device__ uint4 g_woT[1024 * 1024 / 8];          // Wo^T half, [N,K]
__device__ float g_cosT[SS * 32];                 // rope tables
__device__ float g_sinT[SS * 32];

__device__ __forceinline__ uint32_t h2(float a, float b) {
    __half2 h = __floats2half2_rn(a, b);
    return *(uint32_t*)&h;
}
__device__ __forceinline__ void mma_f16(float c[4],
    uint32_t a0, uint32_t a1, uint32_t a2, uint32_t a3,
    uint32_t b0, uint32_t b1)
{
    asm volatile(
        "mma.sync.aligned.m16n8k16.row.col.f32.f16.f16.f32 "
        "{%0,%1,%2,%3}, {%4,%5,%6,%7}, {%8,%9}, {%0,%1,%2,%3};\n"
        : "+f"(c[0]), "+f"(c[1]), "+f"(c[2]), "+f"(c[3])
        : "r"(a0), "r"(a1), "r"(a2), "r"(a3), "r"(b0), "r"(b1));
}
__device__ __forceinline__ void ldsm4(uint32_t d[4], uint32_t saddr) {
    asm volatile("ldmatrix.sync.aligned.m8n8.x4.shared.b16 {%0,%1,%2,%3}, [%4];\n"
        : "=r"(d[0]), "=r"(d[1]), "=r"(d[2]), "=r"(d[3]) : "r"(saddr));
}
__device__ __forceinline__ void ldsm4t(uint32_t d[4], uint32_t saddr) {
    asm volatile("ldmatrix.sync.aligned.m8n8.x4.trans.shared.b16 {%0,%1,%2,%3}, [%4];\n"
        : "=r"(d[0]), "=r"(d[1]), "=r"(d[2]), "=r"(d[3]) : "r"(saddr));
}
#define CP16(dst, src) \
    asm volatile("cp.async.cg.shared.global [%0], [%1], 16;\n" :: "r"(dst), "l"(src))
#define CP_COMMIT()  asm volatile("cp.async.commit_group;\n" ::)
#define CP_WAIT0()   asm volatile("cp.async.wait_group 0;\n" ::)
#define CP_WAIT1()   asm volatile("cp.async.wait_group 1;\n" ::)
#define CP_WAIT2()   asm volatile("cp.async.wait_group 2;\n" ::)

// ============================================================
// helpers: convert x, build rope tables, transpose weights
// ============================================================
__global__ void convert_x(const float4* __restrict__ x, uint2* __restrict__ xh, int n4)
{
    int i = blockIdx.x * blockDim.x + threadIdx.x;
    if (i >= n4) return;
    float4 t = x[i];
    xh[i] = make_uint2(h2(t.x, t.y), h2(t.z, t.w));
}

__global__ void build_cs()
{
    int i = blockIdx.x * blockDim.x + threadIdx.x;
    if (i >= SS * 32) return;
    int s = i >> 5, f = i & 31;
    float theta = powf(10000.0f, -(float)f / 32.0f);
    float sn, cs;
    sincosf((float)s * theta, &sn, &cs);
    g_cosT[i] = cs;
    g_sinT[i] = sn;
}

__global__ void transpose_w(const float* __restrict__ Wq, const float* __restrict__ Wk,
                            const float* __restrict__ Wv, const float* __restrict__ Wo,
                            __half* __restrict__ wqkvT, __half* __restrict__ woT)
{
    __shared__ float tile[32][33];
    const int z = blockIdx.z;
    const float* src; __half* dst; int C;
    if      (z == 0) { src = Wq; dst = wqkvT;               C = 1024; }
    else if (z == 1) { src = Wk; dst = wqkvT + 1024 * 1024; C = 256;  }
    else if (z == 2) { src = Wv; dst = wqkvT + 1280 * 1024; C = 256;  }
    else             { src = Wo; dst = woT;                 C = 1024; }

    int c0 = blockIdx.x * 32;
    if (c0 >= C) return;
    int r0 = blockIdx.y * 32;
    int tx = threadIdx.x, ty = threadIdx.y;

#pragma unroll
    for (int i = 0; i < 4; i++)
        tile[ty + i * 8][tx] = src[(size_t)(r0 + ty + i * 8) * C + c0 + tx];
    __syncthreads();
#pragma unroll
    for (int i = 0; i < 4; i++)
        dst[(size_t)(c0 + ty + i * 8) * 1024 + r0 + tx] =
            __float2half_rn(tile[tx][ty + i * 8]);
}

// ============================================================
// All-half GEMM: C[M,N] = A[M,K] @ Bt[N,K]^T
// 128x128x32 tiles, 256 threads (8 warps, warp tile 32x64),
// cp.async 4-stage pipeline, front-loaded ldmatrix fragments.
// MODE 0: half qkv output + fused RoPE. MODE 1: float out.
// ============================================================
#define GSTR 20
#define G_AWORDS (128 * GSTR)
#define G_STAGE_WORDS (2 * G_AWORDS)
#define G_STAGES 4
#define GEMM_SMEM (G_STAGES * G_STAGE_WORDS * 4)

template<int MODE>
__global__ __launch_bounds__(256, 2) void gemm_h(
    const uint4* __restrict__ A4, const uint4* __restrict__ B4,
    uint32_t* __restrict__ qp, uint32_t* __restrict__ kp, uint32_t* __restrict__ vp,
    float* __restrict__ outp, int K, int KT)
{
    extern __shared__ __align__(16) uint32_t gsm[];
    const uint32_t smA = (uint32_t)__cvta_generic_to_shared(gsm);

    const int tid  = threadIdx.x;
    const int warp = tid >> 5;
    const int lane = tid & 31;
    const int lr   = lane >> 2;
    const int lc   = lane & 3;
    const int g    = lane >> 3;
    const int r8   = lane & 7;
    const int gh   = g & 1;
    const int gv   = g >> 1;
    const int wrow = (warp & 3) * 32;
    const int wcol = (warp >> 2) * 64;
    const long rowBase = (long)blockIdx.y * 128;
    const long colBase = (long)blockIdx.x * 128;

    // loader: threads 0-127 -> A rows, 128-255 -> B rows; 64B per thread per stage
    const int lrow = tid & 127;
    const uint4* srcBase = (tid < 128)
        ? A4 + (size_t)(rowBase + lrow) * (K >> 3)
        : B4 + (size_t)(colBase + lrow) * (K >> 3);
    const uint32_t dstw = (tid < 128 ? 0 : G_AWORDS) + lrow * GSTR;

    float acc[2][8][4];
#pragma unroll
    for (int i = 0; i < 2; i++)
#pragma unroll
        for (int j = 0; j < 8; j++)
#pragma unroll
            for (int r = 0; r < 4; r++) acc[i][j][r] = 0.0f;

    // prologue: stages 0..2
#pragma unroll
    for (int s = 0; s < G_STAGES - 1; s++) {
        uint32_t base = smA + (s * G_STAGE_WORDS + dstw) * 4;
#pragma unroll
        for (int ch = 0; ch < 4; ch++)
            CP16(base + ch * 16, srcBase + s * 4 + ch);
        CP_COMMIT();
    }

    for (int kt = 0; kt < KT; kt++) {
        CP_WAIT2();                 // stage kt data resident
        __syncthreads();

        // issue stage kt + 3
        if (kt + G_STAGES - 1 < KT) {
            int s = (kt + G_STAGES - 1) % G_STAGES;
            uint32_t base = smA + (s * G_STAGE_WORDS + dstw) * 4;
#pragma unroll
            for (int ch = 0; ch < 4; ch++)
                CP16(base + ch * 16, srcBase + (kt + G_STAGES - 1) * 4 + ch);
        }
        CP_COMMIT();

        const uint32_t curA = smA + (kt % G_STAGES) * G_STAGE_WORDS * 4;
        const uint32_t curB = curA + G_AWORDS * 4;

#pragma unroll
        for (int kc = 0; kc < 2; kc++) {
            // front-load ALL fragments for this kc, then burst the mmas
            uint32_t af[2][4], bd[4][4];
#pragma unroll
            for (int ma = 0; ma < 2; ma++)
                ldsm4(af[ma], curA + ((wrow + ma * 16 + gh * 8 + r8) * GSTR + kc * 8 + gv * 4) * 4);
#pragma unroll
            for (int na2 = 0; na2 < 4; na2++)
                ldsm4(bd[na2], curB + ((wcol + na2 * 16 + gv * 8 + r8) * GSTR + kc * 8 + gh * 4) * 4);
#pragma unroll
            for (int na2 = 0; na2 < 4; na2++)
#pragma unroll
                for (int ma = 0; ma < 2; ma++) {
                    mma_f16(acc[ma][2 * na2],     af[ma][0], af[ma][1], af[ma][2], af[ma][3],
                            bd[na2][0], bd[na2][1]);
                    mma_f16(acc[ma][2 * na2 + 1], af[ma][0], af[ma][1], af[ma][2], af[ma][3],
                            bd[na2][2], bd[na2][3]);
                }
        }
    }

    // epilogue
    if (MODE == 0) {
        uint32_t* T; int tstride, toff;
        if (colBase < 1024)      { T = qp; tstride = 1024; toff = (int)colBase; }
        else if (colBase < 1280) { T = kp; tstride = 256;  toff = (int)colBase - 1024; }
        else                     { T = vp; tstride = 256;  toff = (int)colBase - 1280; }
        const bool  doRope = (colBase < 1280);
        const float qscale = (colBase < 1024) ? 0.125f : 1.0f;

#pragma unroll
        for (int ma = 0; ma < 2; ma++) {
            long r0 = rowBase + wrow + ma * 16 + lr;
            if (doRope) {
                int s0 = (int)(r0 & (SS - 1));
                int s1 = (int)((r0 + 8) & (SS - 1));
#pragma unroll
                for (int na = 0; na < 4; na++) {
                    int f = na * 8 + 2 * lc;
                    float2 c0 = *(const float2*)(g_cosT + s0 * 32 + f);
                    float2 n0 = *(const float2*)(g_sinT + s0 * 32 + f);
                    float2 c1 = *(const float2*)(g_cosT + s1 * 32 + f);
                    float2 n1 = *(const float2*)(g_sinT + s1 * 32 + f);
                    float x0 = acc[ma][na][0], x1 = acc[ma][na][1];
                    float y0 = acc[ma][na + 4][0], y1 = acc[ma][na + 4][1];
                    acc[ma][na][0]     = x0 * c0.x - y0 * n0.x;
                    acc[ma][na + 4][0] = y0 * c0.x + x0 * n0.x;
                    acc[ma][na][1]     = x1 * c0.y - y1 * n0.y;
                    acc[ma][na + 4][1] = y1 * c0.y + x1 * n0.y;
                    float x2 = acc[ma][na][2], x3 = acc[ma][na][3];
                    float y2 = acc[ma][na + 4][2], y3 = acc[ma][na + 4][3];
                    acc[ma][na][2]     = x2 * c1.x - y2 * n1.x;
                    acc[ma][na + 4][2] = y2 * c1.x + x2 * n1.x;
                    acc[ma][na][3]     = x3 * c1.y - y3 * n1.y;
                    acc[ma][na + 4][3] = y3 * c1.y + x3 * n1.y;
                }
            }
#pragma unroll
            for (int na = 0; na < 8; na++) {
                int col = toff + wcol + na * 8 + 2 * lc;
                T[(r0 * tstride + col) >> 1] =
                    h2(acc[ma][na][0] * qscale, acc[ma][na][1] * qscale);
                T[((r0 + 8) * tstride + col) >> 1] =
                    h2(acc[ma][na][2] * qscale, acc[ma][na][3] * qscale);
            }
        }
    } else {
#pragma unroll
        for (int ma = 0; ma < 2; ma++) {
            long r0 = rowBase + wrow + ma * 16 + lr;
#pragma unroll
            for (int na = 0; na < 8; na++) {
                int col = (int)colBase + wcol + na * 8 + 2 * lc;
                *(float2*)(outp + r0 * DD + col) =
                    make_float2(acc[ma][na][0], acc[ma][na][1]);
                *(float2*)(outp + (r0 + 8) * DD + col) =
                    make_float2(acc[ma][na][2], acc[ma][na][3]);
            }
        }
    }
}

// ============================================================
// FP16 flash attention: 128-q tiles, 256 threads (8 warps x 16 rows),
// 64-key tiles, cp.async triple-buffered KV, ONE sync per tile.
// ============================================================
#define FSTR 36
#define FLASH_SMEM ((128 + 128 + 3 * 128) * FSTR * 4)

__global__ __launch_bounds__(256) void flash_f16(
    const uint4* __restrict__ Q, const uint4* __restrict__ K,
    const uint4* __restrict__ V, uint32_t* __restrict__ O)
{
    extern __shared__ __align__(16) uint32_t fsm[];
    uint32_t* sQ  = fsm;
    uint32_t* sP  = sQ + 128 * FSTR;
    uint32_t* sKV = sP + 128 * FSTR;

    const int tid  = threadIdx.x;
    const int warp = tid >> 5;
    const int lane = tid & 31;
    const int lr   = lane >> 2;
    const int lc   = lane & 3;
    const int g    = lane >> 3;
    const int r8   = lane & 7;
    const int gh   = g & 1;
    const int gv   = g >> 1;
    const int qt   = gridDim.x - 1 - blockIdx.x;
    const int qb   = qt * 128;
    const int h    = blockIdx.y;
    const int b    = blockIdx.z;
    const int kvh  = h >> 2;
    const int ntiles = 2 * qt + 2;

    const uint32_t sQa  = (uint32_t)__cvta_generic_to_shared(sQ);
    const uint32_t sPa  = (uint32_t)__cvta_generic_to_shared(sP);
    const uint32_t sKVa = (uint32_t)__cvta_generic_to_shared(sKV);

    const int si = tid;
    auto stageKV = [&](int kt, int buf) {
        uint32_t bufa = sKVa + buf * 128 * FSTR * 4;
#pragma unroll
        for (int u = 0; u < 4; u++) {
            int i   = si + u * 256;
            int idx = i & 511;
            int r   = idx >> 3, c = idx & 7;
            const uint4* src = ((i < 512) ? K : V) +
                ((size_t)(b * SS + kt * 64 + r) * NKV + kvh) * 8 + c;
            uint32_t dst = bufa + (((i < 512) ? 0 : 64 * FSTR) + r * FSTR + c * 4) * 4;
            CP16(dst, src);
        }
        CP_COMMIT();
    };

    for (int i = tid; i < 1024; i += 256) {
        int r = i >> 3, c = i & 7;
        *(uint4*)&sQ[r * FSTR + c * 4] = Q[((size_t)(b * SS + qb + r) * NH + h) * 8 + c];
    }

    stageKV(0, 0);
    stageKV(1, 1);

    float acc[8][4];
#pragma unroll
    for (int na = 0; na < 8; na++)
#pragma unroll
        for (int r = 0; r < 4; r++) acc[na][r] = 0.0f;
    float m_lo = -1e30f, m_hi = -1e30f, l_lo = 0.0f, l_hi = 0.0f;

    uint32_t* pw = sP + warp * 16 * FSTR;
    const uint32_t pwa = sPa + warp * 16 * FSTR * 4;
    const int wr_lo = warp * 16;
    uint32_t qf[4][4];
    bool qloaded = false;

    for (int kt = 0; kt < ntiles; kt++) {
        if (kt + 1 < ntiles) CP_WAIT1(); else CP_WAIT0();
        __syncthreads();
        if (kt + 2 < ntiles) stageKV(kt + 2, (kt + 2) % 3);

        if (!qloaded) {
            qloaded = true;
#pragma unroll
            for (int kc = 0; kc < 4; kc++)
                ldsm4(qf[kc], sQa + ((warp * 16 + gh * 8 + r8) * FSTR + kc * 8 + gv * 4) * 4);
        }

        const uint32_t cura = sKVa + (kt % 3) * 128 * FSTR * 4;
        const uint32_t curK = cura;
        const uint32_t curV = cura + 64 * FSTR * 4;

        const int relq = qb + wr_lo - kt * 64;
        if (relq + 15 >= 0) {
            float sc[8][4];
#pragma unroll
            for (int na = 0; na < 8; na++)
                sc[na][0] = sc[na][1] = sc[na][2] = sc[na][3] = 0.0f;
#pragma unroll
            for (int na2 = 0; na2 < 4; na2++) {
#pragma unroll
                for (int kc = 0; kc < 4; kc++) {
                    uint32_t kd[4];
                    ldsm4(kd, curK + ((na2 * 16 + gv * 8 + r8) * FSTR + kc * 8 + gh * 4) * 4);
                    mma_f16(sc[2*na2],     qf[kc][0], qf[kc][1], qf[kc][2], qf[kc][3], kd[0], kd[1]);
                    mma_f16(sc[2*na2 + 1], qf[kc][0], qf[kc][1], qf[kc][2], qf[kc][3], kd[2], kd[3]);
                }
            }

            if (relq < 63) {
#pragma unroll
                for (int na = 0; na < 8; na++) {
                    int col = na * 8 + 2 * lc;
                    if (col     > relq + lr)     sc[na][0] = -1e30f;
                    if (col + 1 > relq + lr)     sc[na][1] = -1e30f;
                    if (col     > relq + lr + 8) sc[na][2] = -1e30f;
                    if (col + 1 > relq + lr + 8) sc[na][3] = -1e30f;
                }
            }

            float rm_lo = -1e30f, rm_hi = -1e30f;
#pragma unroll
            for (int na = 0; na < 8; na++) {
                rm_lo = fmaxf(rm_lo, fmaxf(sc[na][0], sc[na][1]));
                rm_hi = fmaxf(rm_hi, fmaxf(sc[na][2], sc[na][3]));
            }
            rm_lo = fmaxf(rm_lo, __shfl_xor_sync(0xffffffff, rm_lo, 1));
            rm_lo = fmaxf(rm_lo, __shfl_xor_sync(0xffffffff, rm_lo, 2));
            rm_hi = fmaxf(rm_hi, __shfl_xor_sync(0xffffffff, rm_hi, 1));
            rm_hi = fmaxf(rm_hi, __shfl_xor_sync(0xffffffff, rm_hi, 2));

            float mn_lo = fmaxf(m_lo, rm_lo);
            float mn_hi = fmaxf(m_hi, rm_hi);
            float corr_lo = __expf(m_lo - mn_lo);
            float corr_hi = __expf(m_hi - mn_hi);
            m_lo = mn_lo; m_hi = mn_hi;

            float ps_lo = 0.0f, ps_hi = 0.0f;
#pragma unroll
            for (int na = 0; na < 8; na++) {
                float p0 = __expf(sc[na][0] - m_lo);
                float p1 = __expf(sc[na][1] - m_lo);
                float p2 = __expf(sc[na][2] - m_hi);
                float p3 = __expf(sc[na][3] - m_hi);
                ps_lo += p0 + p1;
                ps_hi += p2 + p3;
                pw[lr * FSTR + na * 4 + lc]       = h2(p0, p1);
                pw[(lr + 8) * FSTR + na * 4 + lc] = h2(p2, p3);
                acc[na][0] *= corr_lo; acc[na][1] *= corr_lo;
                acc[na][2] *= corr_hi; acc[na][3] *= corr_hi;
            }
            ps_lo += __shfl_xor_sync(0xffffffff, ps_lo, 1);
            ps_lo += __shfl_xor_sync(0xffffffff, ps_lo, 2);
            ps_hi += __shfl_xor_sync(0xffffffff, ps_hi, 1);
            ps_hi += __shfl_xor_sync(0xffffffff, ps_hi, 2);
            l_lo = l_lo * corr_lo + ps_lo;
            l_hi = l_hi * corr_hi + ps_hi;

            __syncwarp();

#pragma unroll
            for (int kc = 0; kc < 4; kc++) {
                uint32_t pf[4];
                ldsm4(pf, pwa + ((gh * 8 + r8) * FSTR + kc * 8 + gv * 4) * 4);
#pragma unroll
                for (int na2 = 0; na2 < 4; na2++) {
                    uint32_t vd[4];
                    ldsm4t(vd, curV + ((kc * 16 + gh * 8 + r8) * FSTR + na2 * 8 + gv * 4) * 4);
                    mma_f16(acc[2*na2],     pf[0], pf[1], pf[2], pf[3], vd[0], vd[1]);
                    mma_f16(acc[2*na2 + 1], pf[0], pf[1], pf[2], pf[3], vd[2], vd[3]);
                }
            }
        }
    }

    float inv_lo = 1.0f / l_lo;
    float inv_hi = 1.0f / l_hi;
    size_t r0 = (size_t)(b * SS + qb + warp * 16 + lr);
    size_t r1 = r0 + 8;
#pragma unroll
    for (int na = 0; na < 8; na++) {
        int wd = na * 4 + lc;
        O[(r0 * NH + h) * 32 + wd] = h2(acc[na][0] * inv_lo, acc[na][1] * inv_lo);
        O[(r1 * NH + h) * 32 + wd] = h2(acc[na][2] * inv_hi, acc[na][3] * inv_hi);
    }
}

// ============================================================
// launch
// ============================================================
extern "C" void kernel_launch(void* const* d_in, const int* in_sizes, int n_in,
                              void* d_out, int out_size)
{
    const float* x  = (const float*)d_in[0];
    const float* Wq = (const float*)d_in[1];
    const float* Wk = (const float*)d_in[2];
    const float* Wv = (const float*)d_in[3];
    const float* Wo = (const float*)d_in[4];
    float* out = (float*)d_out;

    void *q, *k, *v, *ctx, *xh, *wqkvT, *woT;
    cudaGetSymbolAddress(&q,     g_q);
    cudaGetSymbolAddress(&k,     g_k);
    cudaGetSymbolAddress(&v,     g_v);
    cudaGetSymbolAddress(&ctx,   g_ctx);
    cudaGetSymbolAddress(&xh,    g_xh);
    cudaGetSymbolAddress(&wqkvT, g_wqkvT);
    cudaGetSymbolAddress(&woT,   g_woT);

    const int M = BB * SS;  // 8192

    cudaFuncSetAttribute(gemm_h<0>, cudaFuncAttributeMaxDynamicSharedMemorySize, GEMM_SMEM);
    cudaFuncSetAttribute(gemm_h<1>, cudaFuncAttributeMaxDynamicSharedMemorySize, GEMM_SMEM);
    cudaFuncSetAttribute(flash_f16, cudaFuncAttributeMaxDynamicSharedMemorySize, FLASH_SMEM);

    convert_x<<<(M * DD / 4 + 255) / 256, 256>>>(
        (const float4*)x, (uint2*)xh, M * DD / 4);
    build_cs<<<(SS * 32 + 255) / 256, 256>>>();
    transpose_w<<<dim3(32, 32, 4), dim3(32, 8)>>>(
        Wq, Wk, Wv, Wo, (__half*)wqkvT, (__half*)woT);

    // fused QKV projection + RoPE
    gemm_h<0><<<dim3(12, M / 128), 256, GEMM_SMEM>>>(
        (const uint4*)xh, (const uint4*)wqkvT,
        (uint32_t*)q, (uint32_t*)k, (uint32_t*)v, nullptr, DD, DD / 32);

    // attention
    flash_f16<<<dim3(SS / 128, NH, BB), 256, FLASH_SMEM>>>(
        (const uint4*)q, (const uint4*)k, (const uint4*)v, (uint32_t*)ctx);

    // output projection
    gemm_h<1><<<dim3(8, M / 128), 256, GEMM_SMEM>>>(
        (const uint4*)ctx, (const uint4*)woT,
        nullptr, nullptr, nullptr, out, DD, DD / 32);
}

// round 12
// speedup vs baseline: 1.0956x; 1.0405x over previous
#include <cuda_runtime.h>
#include <cuda_fp16.h>
#include <math.h>
#include <stdint.h>

#define BB   4
#define SS   2048
#define DD   1024
#define NH   16
#define NKV  4
#define DK   64

// -------- scratch (no allocations allowed) --------
__device__ uint4 g_q[BB * SS * NH * DK / 8];
__device__ uint4 g_k[BB * SS * NKV * DK / 8];
__device__ uint4 g_v[BB * SS * NKV * DK / 8];
__device__ uint4 g_ctx[BB * SS * DD / 8];
__device__ uint4 g_xh[BB * SS * DD / 8];          // x in half
__device__ uint4 g_wqkvT[1536 * 1024 / 8];        // [Wq|Wk|Wv]^T half, [N,K]
__device__ uint4 g_woT[1024 * 1024 / 8];          // Wo^T half, [N,K]
__device__ float g_cosT[SS * 32];                 // rope tables
__device__ float g_sinT[SS * 32];

__device__ __forceinline__ uint32_t h2(float a, float b) {
    __half2 h = __floats2half2_rn(a, b);
    return *(uint32_t*)&h;
}
__device__ __forceinline__ void mma_f16(float c[4],
    uint32_t a0, uint32_t a1, uint32_t a2, uint32_t a3,
    uint32_t b0, uint32_t b1)
{
    asm volatile(
        "mma.sync.aligned.m16n8k16.row.col.f32.f16.f16.f32 "
        "{%0,%1,%2,%3}, {%4,%5,%6,%7}, {%8,%9}, {%0,%1,%2,%3};\n"
        : "+f"(c[0]), "+f"(c[1]), "+f"(c[2]), "+f"(c[3])
        : "r"(a0), "r"(a1), "r"(a2), "r"(a3), "r"(b0), "r"(b1));
}
__device__ __forceinline__ void ldsm4(uint32_t d[4], uint32_t saddr) {
    asm volatile("ldmatrix.sync.aligned.m8n8.x4.shared.b16 {%0,%1,%2,%3}, [%4];\n"
        : "=r"(d[0]), "=r"(d[1]), "=r"(d[2]), "=r"(d[3]) : "r"(saddr));
}
__device__ __forceinline__ void ldsm4t(uint32_t d[4], uint32_t saddr) {
    asm volatile("ldmatrix.sync.aligned.m8n8.x4.trans.shared.b16 {%0,%1,%2,%3}, [%4];\n"
        : "=r"(d[0]), "=r"(d[1]), "=r"(d[2]), "=r"(d[3]) : "r"(saddr));
}
#define CP16(dst, src) \
    asm volatile("cp.async.cg.shared.global [%0], [%1], 16;\n" :: "r"(dst), "l"(src))
#define CP_COMMIT()  asm volatile("cp.async.commit_group;\n" ::)
#define CP_WAIT0()   asm volatile("cp.async.wait_group 0;\n" ::)
#define CP_WAIT1()   asm volatile("cp.async.wait_group 1;\n" ::)

// ============================================================
// fused prep: convert x (f32->f16) + build rope tables
// ============================================================
__global__ void prep_kernel(const float4* __restrict__ x, uint2* __restrict__ xh, int n4)
{
    int i = blockIdx.x * blockDim.x + threadIdx.x;
    if (i < n4) {
        float4 t = x[i];
        xh[i] = make_uint2(h2(t.x, t.y), h2(t.z, t.w));
    }
    int j = i - n4;
    if (j >= 0 && j < SS * 32) {
        int s = j >> 5, f = j & 31;
        float theta = powf(10000.0f, -(float)f / 32.0f);
        float sn, cs;
        sincosf((float)s * theta, &sn, &cs);
        g_cosT[j] = cs;
        g_sinT[j] = sn;
    }
}

__global__ void transpose_w(const float* __restrict__ Wq, const float* __restrict__ Wk,
                            const float* __restrict__ Wv, const float* __restrict__ Wo,
                            __half* __restrict__ wqkvT, __half* __restrict__ woT)
{
    __shared__ float tile[32][33];
    const int z = blockIdx.z;
    const float* src; __half* dst; int C;
    if      (z == 0) { src = Wq; dst = wqkvT;               C = 1024; }
    else if (z == 1) { src = Wk; dst = wqkvT + 1024 * 1024; C = 256;  }
    else if (z == 2) { src = Wv; dst = wqkvT + 1280 * 1024; C = 256;  }
    else             { src = Wo; dst = woT;                 C = 1024; }

    int c0 = blockIdx.x * 32;
    if (c0 >= C) return;
    int r0 = blockIdx.y * 32;
    int tx = threadIdx.x, ty = threadIdx.y;

#pragma unroll
    for (int i = 0; i < 4; i++)
        tile[ty + i * 8][tx] = src[(size_t)(r0 + ty + i * 8) * C + c0 + tx];
    __syncthreads();
#pragma unroll
    for (int i = 0; i < 4; i++)
        dst[(size_t)(c0 + ty + i * 8) * 1024 + r0 + tx] =
            __float2half_rn(tile[tx][ty + i * 8]);
}

// ============================================================
// All-half GEMM (R8 config): C[M,N] = A[M,K] @ Bt[N,K]^T
// 128x128x32 tiles, 256 threads (8 warps, warp tile 32x64),
// cp.async 3-stage pipeline, ldmatrix fragments.
// MODE 0: half qkv output + fused RoPE (Q pre-scaled by 0.125*log2e).
// MODE 1: float out.
// ============================================================
#define GSTR 20
#define G_AWORDS (128 * GSTR)
#define G_STAGE_WORDS (2 * G_AWORDS)
#define G_STAGES 3
#define GEMM_SMEM (G_STAGES * G_STAGE_WORDS * 4)

#define QSCALE 0.180336880f   // 0.125 * log2(e)

template<int MODE>
__global__ __launch_bounds__(256, 2) void gemm_h(
    const uint4* __restrict__ A4, const uint4* __restrict__ B4,
    uint32_t* __restrict__ qp, uint32_t* __restrict__ kp, uint32_t* __restrict__ vp,
    float* __restrict__ outp, int K, int KT)
{
    extern __shared__ __align__(16) uint32_t gsm[];
    const uint32_t smA = (uint32_t)__cvta_generic_to_shared(gsm);

    const int tid  = threadIdx.x;
    const int warp = tid >> 5;
    const int lane = tid & 31;
    const int lr   = lane >> 2;
    const int lc   = lane & 3;
    const int g    = lane >> 3;
    const int r8   = lane & 7;
    const int gh   = g & 1;
    const int gv   = g >> 1;
    const int wrow = (warp & 3) * 32;
    const int wcol = (warp >> 2) * 64;
    const long rowBase = (long)blockIdx.y * 128;
    const long colBase = (long)blockIdx.x * 128;

    // loader: threads 0-127 -> A rows, 128-255 -> B rows; 64B per thread
    const int lrow = tid & 127;
    const uint4* srcBase = (tid < 128)
        ? A4 + (size_t)(rowBase + lrow) * (K >> 3)
        : B4 + (size_t)(colBase + lrow) * (K >> 3);
    const uint32_t dstw = (tid < 128 ? 0 : G_AWORDS) + lrow * GSTR;

    float acc[2][8][4];
#pragma unroll
    for (int i = 0; i < 2; i++)
#pragma unroll
        for (int j = 0; j < 8; j++)
#pragma unroll
            for (int r = 0; r < 4; r++) acc[i][j][r] = 0.0f;

    // prologue: stages 0, 1
#pragma unroll
    for (int s = 0; s < G_STAGES - 1; s++) {
        uint32_t base = smA + (s * G_STAGE_WORDS + dstw) * 4;
#pragma unroll
        for (int ch = 0; ch < 4; ch++)
            CP16(base + ch * 16, srcBase + s * 4 + ch);
        CP_COMMIT();
    }

    for (int kt = 0; kt < KT; kt++) {
        CP_WAIT1();
        __syncthreads();

        // issue stage kt + STAGES-1
        if (kt + G_STAGES - 1 < KT) {
            int s = (kt + G_STAGES - 1) % G_STAGES;
            uint32_t base = smA + (s * G_STAGE_WORDS + dstw) * 4;
#pragma unroll
            for (int ch = 0; ch < 4; ch++)
                CP16(base + ch * 16, srcBase + (kt + G_STAGES - 1) * 4 + ch);
        }
        CP_COMMIT();

        const uint32_t curA = smA + (kt % G_STAGES) * G_STAGE_WORDS * 4;
        const uint32_t curB = curA + G_AWORDS * 4;

#pragma unroll
        for (int kc = 0; kc < 2; kc++) {
            uint32_t af[2][4];
#pragma unroll
            for (int ma = 0; ma < 2; ma++)
                ldsm4(af[ma], curA + ((wrow + ma * 16 + gh * 8 + r8) * GSTR + kc * 8 + gv * 4) * 4);
#pragma unroll
            for (int na2 = 0; na2 < 4; na2++) {
                uint32_t bd[4];
                ldsm4(bd, curB + ((wcol + na2 * 16 + gv * 8 + r8) * GSTR + kc * 8 + gh * 4) * 4);
#pragma unroll
                for (int ma = 0; ma < 2; ma++) {
                    mma_f16(acc[ma][2 * na2],     af[ma][0], af[ma][1], af[ma][2], af[ma][3], bd[0], bd[1]);
                    mma_f16(acc[ma][2 * na2 + 1], af[ma][0], af[ma][1], af[ma][2], af[ma][3], bd[2], bd[3]);
                }
            }
        }
    }

    // epilogue
    if (MODE == 0) {
        uint32_t* T; int tstride, toff;
        if (colBase < 1024)      { T = qp; tstride = 1024; toff = (int)colBase; }
        else if (colBase < 1280) { T = kp; tstride = 256;  toff = (int)colBase - 1024; }
        else                     { T = vp; tstride = 256;  toff = (int)colBase - 1280; }
        const bool  doRope = (colBase < 1280);
        const float qscale = (colBase < 1024) ? QSCALE : 1.0f;

#pragma unroll
        for (int ma = 0; ma < 2; ma++) {
            long r0 = rowBase + wrow + ma * 16 + lr;
            if (doRope) {
                int s0 = (int)(r0 & (SS - 1));
                int s1 = (int)((r0 + 8) & (SS - 1));
#pragma unroll
                for (int na = 0; na < 4; na++) {
                    int f = na * 8 + 2 * lc;
                    float2 c0 = *(const float2*)(g_cosT + s0 * 32 + f);
                    float2 n0 = *(const float2*)(g_sinT + s0 * 32 + f);
                    float2 c1 = *(const float2*)(g_cosT + s1 * 32 + f);
                    float2 n1 = *(const float2*)(g_sinT + s1 * 32 + f);
                    float x0 = acc[ma][na][0], x1 = acc[ma][na][1];
                    float y0 = acc[ma][na + 4][0], y1 = acc[ma][na + 4][1];
                    acc[ma][na][0]     = x0 * c0.x - y0 * n0.x;
                    acc[ma][na + 4][0] = y0 * c0.x + x0 * n0.x;
                    acc[ma][na][1]     = x1 * c0.y - y1 * n0.y;
                    acc[ma][na + 4][1] = y1 * c0.y + x1 * n0.y;
                    float x2 = acc[ma][na][2], x3 = acc[ma][na][3];
                    float y2 = acc[ma][na + 4][2], y3 = acc[ma][na + 4][3];
                    acc[ma][na][2]     = x2 * c1.x - y2 * n1.x;
                    acc[ma][na + 4][2] = y2 * c1.x + x2 * n1.x;
                    acc[ma][na][3]     = x3 * c1.y - y3 * n1.y;
                    acc[ma][na + 4][3] = y3 * c1.y + x3 * n1.y;
                }
            }
#pragma unroll
            for (int na = 0; na < 8; na++) {
                int col = toff + wcol + na * 8 + 2 * lc;
                T[(r0 * tstride + col) >> 1] =
                    h2(acc[ma][na][0] * qscale, acc[ma][na][1] * qscale);
                T[((r0 + 8) * tstride + col) >> 1] =
                    h2(acc[ma][na][2] * qscale, acc[ma][na][3] * qscale);
            }
        }
    } else {
#pragma unroll
        for (int ma = 0; ma < 2; ma++) {
            long r0 = rowBase + wrow + ma * 16 + lr;
#pragma unroll
            for (int na = 0; na < 8; na++) {
                int col = (int)colBase + wcol + na * 8 + 2 * lc;
                *(float2*)(outp + r0 * DD + col) =
                    make_float2(acc[ma][na][0], acc[ma][na][1]);
                *(float2*)(outp + (r0 + 8) * DD + col) =
                    make_float2(acc[ma][na][2], acc[ma][na][3]);
            }
        }
    }
}

// ============================================================
// FP16 flash attention: 128-q tiles, 256 threads (8 warps x 16 rows),
// 64-key tiles, cp.async triple-buffered KV, ONE sync per tile.
// Softmax in log2 domain (Q pre-scaled by 0.125*log2e; exp2f).
// ============================================================
#define FSTR 36
#define FLASH_SMEM ((128 + 128 + 3 * 128) * FSTR * 4)

__global__ __launch_bounds__(256) void flash_f16(
    const uint4* __restrict__ Q, const uint4* __restrict__ K,
    const uint4* __restrict__ V, uint32_t* __restrict__ O)
{
    extern __shared__ __align__(16) uint32_t fsm[];
    uint32_t* sQ  = fsm;
    uint32_t* sP  = sQ + 128 * FSTR;
    uint32_t* sKV = sP + 128 * FSTR;

    const int tid  = threadIdx.x;
    const int warp = tid >> 5;
    const int lane = tid & 31;
    const int lr   = lane >> 2;
    const int lc   = lane & 3;
    const int g    = lane >> 3;
    const int r8   = lane & 7;
    const int gh   = g & 1;
    const int gv   = g >> 1;
    const int qt   = gridDim.x - 1 - blockIdx.x;
    const int qb   = qt * 128;
    const int h    = blockIdx.y;
    const int b    = blockIdx.z;
    const int kvh  = h >> 2;
    const int ntiles = 2 * qt + 2;

    const uint32_t sQa  = (uint32_t)__cvta_generic_to_shared(sQ);
    const uint32_t sPa  = (uint32_t)__cvta_generic_to_shared(sP);
    const uint32_t sKVa = (uint32_t)__cvta_generic_to_shared(sKV);

    const int si = tid;
    auto stageKV = [&](int kt, int buf) {
        uint32_t bufa = sKVa + buf * 128 * FSTR * 4;
#pragma unroll
        for (int u = 0; u < 4; u++) {
            int i   = si + u * 256;
            int idx = i & 511;
            int r   = idx >> 3, c = idx & 7;
            const uint4* src = ((i < 512) ? K : V) +
                ((size_t)(b * SS + kt * 64 + r) * NKV + kvh) * 8 + c;
            uint32_t dst = bufa + (((i < 512) ? 0 : 64 * FSTR) + r * FSTR + c * 4) * 4;
            CP16(dst, src);
        }
        CP_COMMIT();
    };

    for (int i = tid; i < 1024; i += 256) {
        int r = i >> 3, c = i & 7;
        *(uint4*)&sQ[r * FSTR + c * 4] = Q[((size_t)(b * SS + qb + r) * NH + h) * 8 + c];
    }

    stageKV(0, 0);
    stageKV(1, 1);

    float acc[8][4];
#pragma unroll
    for (int na = 0; na < 8; na++)
#pragma unroll
        for (int r = 0; r < 4; r++) acc[na][r] = 0.0f;
    float m_lo = -1e30f, m_hi = -1e30f, l_lo = 0.0f, l_hi = 0.0f;

    uint32_t* pw = sP + warp * 16 * FSTR;
    const uint32_t pwa = sPa + warp * 16 * FSTR * 4;
    const int wr_lo = warp * 16;
    uint32_t qf[4][4];
    bool qloaded = false;

    for (int kt = 0; kt < ntiles; kt++) {
        if (kt + 1 < ntiles) CP_WAIT1(); else CP_WAIT0();
        __syncthreads();
        if (kt + 2 < ntiles) stageKV(kt + 2, (kt + 2) % 3);

        if (!qloaded) {
            qloaded = true;
#pragma unroll
            for (int kc = 0; kc < 4; kc++)
                ldsm4(qf[kc], sQa + ((warp * 16 + gh * 8 + r8) * FSTR + kc * 8 + gv * 4) * 4);
        }

        const uint32_t cura = sKVa + (kt % 3) * 128 * FSTR * 4;
        const uint32_t curK = cura;
        const uint32_t curV = cura + 64 * FSTR * 4;

        const int relq = qb + wr_lo - kt * 64;
        if (relq + 15 >= 0) {
            float sc[8][4];
#pragma unroll
            for (int na = 0; na < 8; na++)
                sc[na][0] = sc[na][1] = sc[na][2] = sc[na][3] = 0.0f;
#pragma unroll
            for (int na2 = 0; na2 < 4; na2++) {
#pragma unroll
                for (int kc = 0; kc < 4; kc++) {
                    uint32_t kd[4];
                    ldsm4(kd, curK + ((na2 * 16 + gv * 8 + r8) * FSTR + kc * 8 + gh * 4) * 4);
                    mma_f16(sc[2*na2],     qf[kc][0], qf[kc][1], qf[kc][2], qf[kc][3], kd[0], kd[1]);
                    mma_f16(sc[2*na2 + 1], qf[kc][0], qf[kc][1], qf[kc][2], qf[kc][3], kd[2], kd[3]);
                }
            }

            if (relq < 63) {
#pragma unroll
                for (int na = 0; na < 8; na++) {
                    int col = na * 8 + 2 * lc;
                    if (col     > relq + lr)     sc[na][0] = -1e30f;
                    if (col + 1 > relq + lr)     sc[na][1] = -1e30f;
                    if (col     > relq + lr + 8) sc[na][2] = -1e30f;
                    if (col + 1 > relq + lr + 8) sc[na][3] = -1e30f;
                }
            }

            float rm_lo = -1e30f, rm_hi = -1e30f;
#pragma unroll
            for (int na = 0; na < 8; na++) {
                rm_lo = fmaxf(rm_lo, fmaxf(sc[na][0], sc[na][1]));
                rm_hi = fmaxf(rm_hi, fmaxf(sc[na][2], sc[na][3]));
            }
            rm_lo = fmaxf(rm_lo, __shfl_xor_sync(0xffffffff, rm_lo, 1));
            rm_lo = fmaxf(rm_lo, __shfl_xor_sync(0xffffffff, rm_lo, 2));
            rm_hi = fmaxf(rm_hi, __shfl_xor_sync(0xffffffff, rm_hi, 1));
            rm_hi = fmaxf(rm_hi, __shfl_xor_sync(0xffffffff, rm_hi, 2));

            float mn_lo = fmaxf(m_lo, rm_lo);
            float mn_hi = fmaxf(m_hi, rm_hi);
            float corr_lo = exp2f(m_lo - mn_lo);
            float corr_hi = exp2f(m_hi - mn_hi);
            m_lo = mn_lo; m_hi = mn_hi;

            float ps_lo = 0.0f, ps_hi = 0.0f;
#pragma unroll
            for (int na = 0; na < 8; na++) {
                float p0 = exp2f(sc[na][0] - m_lo);
                float p1 = exp2f(sc[na][1] - m_lo);
                float p2 = exp2f(sc[na][2] - m_hi);
                float p3 = exp2f(sc[na][3] - m_hi);
                ps_lo += p0 + p1;
                ps_hi += p2 + p3;
                pw[lr * FSTR + na * 4 + lc]       = h2(p0, p1);
                pw[(lr + 8) * FSTR + na * 4 + lc] = h2(p2, p3);
                acc[na][0] *= corr_lo; acc[na][1] *= corr_lo;
                acc[na][2] *= corr_hi; acc[na][3] *= corr_hi;
            }
            ps_lo += __shfl_xor_sync(0xffffffff, ps_lo, 1);
            ps_lo += __shfl_xor_sync(0xffffffff, ps_lo, 2);
            ps_hi += __shfl_xor_sync(0xffffffff, ps_hi, 1);
            ps_hi += __shfl_xor_sync(0xffffffff, ps_hi, 2);
            l_lo = l_lo * corr_lo + ps_lo;
            l_hi = l_hi * corr_hi + ps_hi;

            __syncwarp();

#pragma unroll
            for (int kc = 0; kc < 4; kc++) {
                uint32_t pf[4];
                ldsm4(pf, pwa + ((gh * 8 + r8) * FSTR + kc * 8 + gv * 4) * 4);
#pragma unroll
                for (int na2 = 0; na2 < 4; na2++) {
                    uint32_t vd[4];
                    ldsm4t(vd, curV + ((kc * 16 + gh * 8 + r8) * FSTR + na2 * 8 + gv * 4) * 4);
                    mma_f16(acc[2*na2],     pf[0], pf[1], pf[2], pf[3], vd[0], vd[1]);
                    mma_f16(acc[2*na2 + 1], pf[0], pf[1], pf[2], pf[3], vd[2], vd[3]);
                }
            }
        }
    }

    float inv_lo = 1.0f / l_lo;
    float inv_hi = 1.0f / l_hi;
    size_t r0 = (size_t)(b * SS + qb + warp * 16 + lr);
    size_t r1 = r0 + 8;
#pragma unroll
    for (int na = 0; na < 8; na++) {
        int wd = na * 4 + lc;
        O[(r0 * NH + h) * 32 + wd] = h2(acc[na][0] * inv_lo, acc[na][1] * inv_lo);
        O[(r1 * NH + h) * 32 + wd] = h2(acc[na][2] * inv_hi, acc[na][3] * inv_hi);
    }
}

// ============================================================
// launch
// ============================================================
extern "C" void kernel_launch(void* const* d_in, const int* in_sizes, int n_in,
                              void* d_out, int out_size)
{
    const float* x  = (const float*)d_in[0];
    const float* Wq = (const float*)d_in[1];
    const float* Wk = (const float*)d_in[2];
    const float* Wv = (const float*)d_in[3];
    const float* Wo = (const float*)d_in[4];
    float* out = (float*)d_out;

    void *q, *k, *v, *ctx, *xh, *wqkvT, *woT;
    cudaGetSymbolAddress(&q,     g_q);
    cudaGetSymbolAddress(&k,     g_k);
    cudaGetSymbolAddress(&v,     g_v);
    cudaGetSymbolAddress(&ctx,   g_ctx);
    cudaGetSymbolAddress(&xh,    g_xh);
    cudaGetSymbolAddress(&wqkvT, g_wqkvT);
    cudaGetSymbolAddress(&woT,   g_woT);

    const int M = BB * SS;  // 8192

    cudaFuncSetAttribute(gemm_h<0>, cudaFuncAttributeMaxDynamicSharedMemorySize, GEMM_SMEM);
    cudaFuncSetAttribute(gemm_h<1>, cudaFuncAttributeMaxDynamicSharedMemorySize, GEMM_SMEM);
    cudaFuncSetAttribute(flash_f16, cudaFuncAttributeMaxDynamicSharedMemorySize, FLASH_SMEM);

    // fused prep: x conversion + rope tables
    {
        int n4 = M * DD / 4;
        int tot = n4 + SS * 32;
        prep_kernel<<<(tot + 255) / 256, 256>>>((const float4*)x, (uint2*)xh, n4);
    }
    transpose_w<<<dim3(32, 32, 4), dim3(32, 8)>>>(
        Wq, Wk, Wv, Wo, (__half*)wqkvT, (__half*)woT);

    // fused QKV projection + RoPE
    gemm_h<0><<<dim3(12, M / 128), 256, GEMM_SMEM>>>(
        (const uint4*)xh, (const uint4*)wqkvT,
        (uint32_t*)q, (uint32_t*)k, (uint32_t*)v, nullptr, DD, DD / 32);

    // attention
    flash_f16<<<dim3(SS / 128, NH, BB), 256, FLASH_SMEM>>>(
        (const uint4*)q, (const uint4*)k, (const uint4*)v, (uint32_t*)ctx);

    // output projection
    gemm_h<1><<<dim3(8, M / 128), 256, GEMM_SMEM>>>(
        (const uint4*)ctx, (const uint4*)woT,
        nullptr, nullptr, nullptr, out, DD, DD / 32);
}

// round 13
// speedup vs baseline: 1.1227x; 1.0247x over previous
#include <cuda_runtime.h>
#include <cuda_fp16.h>
#include <math.h>
#include <stdint.h>

#define BB   4
#define SS   2048
#define DD   1024
#define NH   16
#define NKV  4
#define DK   64

// -------- scratch (no allocations allowed) --------
__device__ uint4 g_q[BB * SS * NH * DK / 8];
__device__ uint4 g_k[BB * SS * NKV * DK / 8];
__device__ uint4 g_v[BB * SS * NKV * DK / 8];
__device__ uint4 g_ctx[BB * SS * DD / 8];
__device__ uint4 g_xh[BB * SS * DD / 8];          // x in half
__device__ uint4 g_wqkvT[1536 * 1024 / 8];        // [Wq|Wk|Wv]^T half, [N,K]
__device__ uint4 g_woT[1024 * 1024 / 8];          // Wo^T half, [N,K]
__device__ float g_cosT[SS * 32];                 // rope tables
__device__ float g_sinT[SS * 32];

__device__ __forceinline__ uint32_t h2(float a, float b) {
    __half2 h = __floats2half2_rn(a, b);
    return *(uint32_t*)&h;
}
__device__ __forceinline__ void mma_f16(float c[4],
    uint32_t a0, uint32_t a1, uint32_t a2, uint32_t a3,
    uint32_t b0, uint32_t b1)
{
    asm volatile(
        "mma.sync.aligned.m16n8k16.row.col.f32.f16.f16.f32 "
        "{%0,%1,%2,%3}, {%4,%5,%6,%7}, {%8,%9}, {%0,%1,%2,%3};\n"
        : "+f"(c[0]), "+f"(c[1]), "+f"(c[2]), "+f"(c[3])
        : "r"(a0), "r"(a1), "r"(a2), "r"(a3), "r"(b0), "r"(b1));
}
__device__ __forceinline__ void ldsm4(uint32_t d[4], uint32_t saddr) {
    asm volatile("ldmatrix.sync.aligned.m8n8.x4.shared.b16 {%0,%1,%2,%3}, [%4];\n"
        : "=r"(d[0]), "=r"(d[1]), "=r"(d[2]), "=r"(d[3]) : "r"(saddr));
}
__device__ __forceinline__ void ldsm4t(uint32_t d[4], uint32_t saddr) {
    asm volatile("ldmatrix.sync.aligned.m8n8.x4.trans.shared.b16 {%0,%1,%2,%3}, [%4];\n"
        : "=r"(d[0]), "=r"(d[1]), "=r"(d[2]), "=r"(d[3]) : "r"(saddr));
}
#define CP16(dst, src) \
    asm volatile("cp.async.cg.shared.global [%0], [%1], 16;\n" :: "r"(dst), "l"(src))
#define CP_COMMIT()  asm volatile("cp.async.commit_group;\n" ::)
#define CP_WAIT0()   asm volatile("cp.async.wait_group 0;\n" ::)
#define CP_WAIT1()   asm volatile("cp.async.wait_group 1;\n" ::)

// ============================================================
// fused prep: convert x (f32->f16) + build rope tables
// ============================================================
__global__ void prep_kernel(const float4* __restrict__ x, uint2* __restrict__ xh, int n4)
{
    int i = blockIdx.x * blockDim.x + threadIdx.x;
    if (i < n4) {
        float4 t = x[i];
        xh[i] = make_uint2(h2(t.x, t.y), h2(t.z, t.w));
    }
    int j = i - n4;
    if (j >= 0 && j < SS * 32) {
        int s = j >> 5, f = j & 31;
        float theta = powf(10000.0f, -(float)f / 32.0f);
        float sn, cs;
        sincosf((float)s * theta, &sn, &cs);
        g_cosT[j] = cs;
        g_sinT[j] = sn;
    }
}

__global__ void transpose_w(const float* __restrict__ Wq, const float* __restrict__ Wk,
                            const float* __restrict__ Wv, const float* __restrict__ Wo,
                            __half* __restrict__ wqkvT, __half* __restrict__ woT)
{
    __shared__ float tile[32][33];
    const int z = blockIdx.z;
    const float* src; __half* dst; int C;
    if      (z == 0) { src = Wq; dst = wqkvT;               C = 1024; }
    else if (z == 1) { src = Wk; dst = wqkvT + 1024 * 1024; C = 256;  }
    else if (z == 2) { src = Wv; dst = wqkvT + 1280 * 1024; C = 256;  }
    else             { src = Wo; dst = woT;                 C = 1024; }

    int c0 = blockIdx.x * 32;
    if (c0 >= C) return;
    int r0 = blockIdx.y * 32;
    int tx = threadIdx.x, ty = threadIdx.y;

#pragma unroll
    for (int i = 0; i < 4; i++)
        tile[ty + i * 8][tx] = src[(size_t)(r0 + ty + i * 8) * C + c0 + tx];
    __syncthreads();
#pragma unroll
    for (int i = 0; i < 4; i++)
        dst[(size_t)(c0 + ty + i * 8) * 1024 + r0 + tx] =
            __float2half_rn(tile[tx][ty + i * 8]);
}

// ============================================================
// All-half GEMM (R8 config): C[M,N] = A[M,K] @ Bt[N,K]^T
// 128x128x32 tiles, 256 threads (8 warps, warp tile 32x64),
// cp.async 3-stage pipeline, ldmatrix fragments.
// MODE 0: half qkv output + fused RoPE (Q pre-scaled by 0.125*log2e).
// MODE 1: float out.
// ============================================================
#define GSTR 20
#define G_AWORDS (128 * GSTR)
#define G_STAGE_WORDS (2 * G_AWORDS)
#define G_STAGES 3
#define GEMM_SMEM (G_STAGES * G_STAGE_WORDS * 4)

#define QSCALE 0.180336880f   // 0.125 * log2(e)

template<int MODE>
__global__ __launch_bounds__(256, 2) void gemm_h(
    const uint4* __restrict__ A4, const uint4* __restrict__ B4,
    uint32_t* __restrict__ qp, uint32_t* __restrict__ kp, uint32_t* __restrict__ vp,
    float* __restrict__ outp, int K, int KT)
{
    extern __shared__ __align__(16) uint32_t gsm[];
    const uint32_t smA = (uint32_t)__cvta_generic_to_shared(gsm);

    const int tid  = threadIdx.x;
    const int warp = tid >> 5;
    const int lane = tid & 31;
    const int lr   = lane >> 2;
    const int lc   = lane & 3;
    const int g    = lane >> 3;
    const int r8   = lane & 7;
    const int gh   = g & 1;
    const int gv   = g >> 1;
    const int wrow = (warp & 3) * 32;
    const int wcol = (warp >> 2) * 64;
    const long rowBase = (long)blockIdx.y * 128;
    const long colBase = (long)blockIdx.x * 128;

    const int lrow = tid & 127;
    const uint4* srcBase = (tid < 128)
        ? A4 + (size_t)(rowBase + lrow) * (K >> 3)
        : B4 + (size_t)(colBase + lrow) * (K >> 3);
    const uint32_t dstw = (tid < 128 ? 0 : G_AWORDS) + lrow * GSTR;

    float acc[2][8][4];
#pragma unroll
    for (int i = 0; i < 2; i++)
#pragma unroll
        for (int j = 0; j < 8; j++)
#pragma unroll
            for (int r = 0; r < 4; r++) acc[i][j][r] = 0.0f;

#pragma unroll
    for (int s = 0; s < G_STAGES - 1; s++) {
        uint32_t base = smA + (s * G_STAGE_WORDS + dstw) * 4;
#pragma unroll
        for (int ch = 0; ch < 4; ch++)
            CP16(base + ch * 16, srcBase + s * 4 + ch);
        CP_COMMIT();
    }

    for (int kt = 0; kt < KT; kt++) {
        CP_WAIT1();
        __syncthreads();

        if (kt + G_STAGES - 1 < KT) {
            int s = (kt + G_STAGES - 1) % G_STAGES;
            uint32_t base = smA + (s * G_STAGE_WORDS + dstw) * 4;
#pragma unroll
            for (int ch = 0; ch < 4; ch++)
                CP16(base + ch * 16, srcBase + (kt + G_STAGES - 1) * 4 + ch);
        }
        CP_COMMIT();

        const uint32_t curA = smA + (kt % G_STAGES) * G_STAGE_WORDS * 4;
        const uint32_t curB = curA + G_AWORDS * 4;

#pragma unroll
        for (int kc = 0; kc < 2; kc++) {
            uint32_t af[2][4];
#pragma unroll
            for (int ma = 0; ma < 2; ma++)
                ldsm4(af[ma], curA + ((wrow + ma * 16 + gh * 8 + r8) * GSTR + kc * 8 + gv * 4) * 4);
#pragma unroll
            for (int na2 = 0; na2 < 4; na2++) {
                uint32_t bd[4];
                ldsm4(bd, curB + ((wcol + na2 * 16 + gv * 8 + r8) * GSTR + kc * 8 + gh * 4) * 4);
#pragma unroll
                for (int ma = 0; ma < 2; ma++) {
                    mma_f16(acc[ma][2 * na2],     af[ma][0], af[ma][1], af[ma][2], af[ma][3], bd[0], bd[1]);
                    mma_f16(acc[ma][2 * na2 + 1], af[ma][0], af[ma][1], af[ma][2], af[ma][3], bd[2], bd[3]);
                }
            }
        }
    }

    // epilogue
    if (MODE == 0) {
        uint32_t* T; int tstride, toff;
        if (colBase < 1024)      { T = qp; tstride = 1024; toff = (int)colBase; }
        else if (colBase < 1280) { T = kp; tstride = 256;  toff = (int)colBase - 1024; }
        else                     { T = vp; tstride = 256;  toff = (int)colBase - 1280; }
        const bool  doRope = (colBase < 1280);
        const float qscale = (colBase < 1024) ? QSCALE : 1.0f;

#pragma unroll
        for (int ma = 0; ma < 2; ma++) {
            long r0 = rowBase + wrow + ma * 16 + lr;
            if (doRope) {
                int s0 = (int)(r0 & (SS - 1));
                int s1 = (int)((r0 + 8) & (SS - 1));
#pragma unroll
                for (int na = 0; na < 4; na++) {
                    int f = na * 8 + 2 * lc;
                    float2 c0 = *(const float2*)(g_cosT + s0 * 32 + f);
                    float2 n0 = *(const float2*)(g_sinT + s0 * 32 + f);
                    float2 c1 = *(const float2*)(g_cosT + s1 * 32 + f);
                    float2 n1 = *(const float2*)(g_sinT + s1 * 32 + f);
                    float x0 = acc[ma][na][0], x1 = acc[ma][na][1];
                    float y0 = acc[ma][na + 4][0], y1 = acc[ma][na + 4][1];
                    acc[ma][na][0]     = x0 * c0.x - y0 * n0.x;
                    acc[ma][na + 4][0] = y0 * c0.x + x0 * n0.x;
                    acc[ma][na][1]     = x1 * c0.y - y1 * n0.y;
                    acc[ma][na + 4][1] = y1 * c0.y + x1 * n0.y;
                    float x2 = acc[ma][na][2], x3 = acc[ma][na][3];
                    float y2 = acc[ma][na + 4][2], y3 = acc[ma][na + 4][3];
                    acc[ma][na][2]     = x2 * c1.x - y2 * n1.x;
                    acc[ma][na + 4][2] = y2 * c1.x + x2 * n1.x;
                    acc[ma][na][3]     = x3 * c1.y - y3 * n1.y;
                    acc[ma][na + 4][3] = y3 * c1.y + x3 * n1.y;
                }
            }
#pragma unroll
            for (int na = 0; na < 8; na++) {
                int col = toff + wcol + na * 8 + 2 * lc;
                T[(r0 * tstride + col) >> 1] =
                    h2(acc[ma][na][0] * qscale, acc[ma][na][1] * qscale);
                T[((r0 + 8) * tstride + col) >> 1] =
                    h2(acc[ma][na][2] * qscale, acc[ma][na][3] * qscale);
            }
        }
    } else {
#pragma unroll
        for (int ma = 0; ma < 2; ma++) {
            long r0 = rowBase + wrow + ma * 16 + lr;
#pragma unroll
            for (int na = 0; na < 8; na++) {
                int col = (int)colBase + wcol + na * 8 + 2 * lc;
                *(float2*)(outp + r0 * DD + col) =
                    make_float2(acc[ma][na][0], acc[ma][na][1]);
                *(float2*)(outp + (r0 + 8) * DD + col) =
                    make_float2(acc[ma][na][2], acc[ma][na][3]);
            }
        }
    }
}

// ============================================================
// FP16 flash attention: 128-q tiles, 256 threads (8 warps x 16 rows),
// 64-key tiles, cp.async triple-buffered KV, ONE sync per tile.
// Softmax in log2 domain; P kept in REGISTERS (c-frag == a-frag pairing).
// ============================================================
#define FSTR 36
#define FLASH_SMEM ((128 + 3 * 128) * FSTR * 4)

__global__ __launch_bounds__(256) void flash_f16(
    const uint4* __restrict__ Q, const uint4* __restrict__ K,
    const uint4* __restrict__ V, uint32_t* __restrict__ O)
{
    extern __shared__ __align__(16) uint32_t fsm[];
    uint32_t* sQ  = fsm;
    uint32_t* sKV = sQ + 128 * FSTR;

    const int tid  = threadIdx.x;
    const int warp = tid >> 5;
    const int lane = tid & 31;
    const int lr   = lane >> 2;
    const int lc   = lane & 3;
    const int g    = lane >> 3;
    const int r8   = lane & 7;
    const int gh   = g & 1;
    const int gv   = g >> 1;
    const int qt   = gridDim.x - 1 - blockIdx.x;
    const int qb   = qt * 128;
    const int h    = blockIdx.y;
    const int b    = blockIdx.z;
    const int kvh  = h >> 2;
    const int ntiles = 2 * qt + 2;

    const uint32_t sQa  = (uint32_t)__cvta_generic_to_shared(sQ);
    const uint32_t sKVa = (uint32_t)__cvta_generic_to_shared(sKV);

    const int si = tid;
    auto stageKV = [&](int kt, int buf) {
        uint32_t bufa = sKVa + buf * 128 * FSTR * 4;
#pragma unroll
        for (int u = 0; u < 4; u++) {
            int i   = si + u * 256;
            int idx = i & 511;
            int r   = idx >> 3, c = idx & 7;
            const uint4* src = ((i < 512) ? K : V) +
                ((size_t)(b * SS + kt * 64 + r) * NKV + kvh) * 8 + c;
            uint32_t dst = bufa + (((i < 512) ? 0 : 64 * FSTR) + r * FSTR + c * 4) * 4;
            CP16(dst, src);
        }
        CP_COMMIT();
    };

    for (int i = tid; i < 1024; i += 256) {
        int r = i >> 3, c = i & 7;
        *(uint4*)&sQ[r * FSTR + c * 4] = Q[((size_t)(b * SS + qb + r) * NH + h) * 8 + c];
    }

    stageKV(0, 0);
    stageKV(1, 1);

    float acc[8][4];
#pragma unroll
    for (int na = 0; na < 8; na++)
#pragma unroll
        for (int r = 0; r < 4; r++) acc[na][r] = 0.0f;
    float m_lo = -1e30f, m_hi = -1e30f, l_lo = 0.0f, l_hi = 0.0f;

    const int wr_lo = warp * 16;
    uint32_t qf[4][4];
    bool qloaded = false;

    for (int kt = 0; kt < ntiles; kt++) {
        if (kt + 1 < ntiles) CP_WAIT1(); else CP_WAIT0();
        __syncthreads();
        if (kt + 2 < ntiles) stageKV(kt + 2, (kt + 2) % 3);

        if (!qloaded) {
            qloaded = true;
#pragma unroll
            for (int kc = 0; kc < 4; kc++)
                ldsm4(qf[kc], sQa + ((warp * 16 + gh * 8 + r8) * FSTR + kc * 8 + gv * 4) * 4);
        }

        const uint32_t cura = sKVa + (kt % 3) * 128 * FSTR * 4;
        const uint32_t curK = cura;
        const uint32_t curV = cura + 64 * FSTR * 4;

        const int relq = qb + wr_lo - kt * 64;
        if (relq + 15 >= 0) {
            float sc[8][4];
#pragma unroll
            for (int na = 0; na < 8; na++)
                sc[na][0] = sc[na][1] = sc[na][2] = sc[na][3] = 0.0f;
#pragma unroll
            for (int na2 = 0; na2 < 4; na2++) {
#pragma unroll
                for (int kc = 0; kc < 4; kc++) {
                    uint32_t kd[4];
                    ldsm4(kd, curK + ((na2 * 16 + gv * 8 + r8) * FSTR + kc * 8 + gh * 4) * 4);
                    mma_f16(sc[2*na2],     qf[kc][0], qf[kc][1], qf[kc][2], qf[kc][3], kd[0], kd[1]);
                    mma_f16(sc[2*na2 + 1], qf[kc][0], qf[kc][1], qf[kc][2], qf[kc][3], kd[2], kd[3]);
                }
            }

            if (relq < 63) {
#pragma unroll
                for (int na = 0; na < 8; na++) {
                    int col = na * 8 + 2 * lc;
                    if (col     > relq + lr)     sc[na][0] = -1e30f;
                    if (col + 1 > relq + lr)     sc[na][1] = -1e30f;
                    if (col     > relq + lr + 8) sc[na][2] = -1e30f;
                    if (col + 1 > relq + lr + 8) sc[na][3] = -1e30f;
                }
            }

            float rm_lo = -1e30f, rm_hi = -1e30f;
#pragma unroll
            for (int na = 0; na < 8; na++) {
                rm_lo = fmaxf(rm_lo, fmaxf(sc[na][0], sc[na][1]));
                rm_hi = fmaxf(rm_hi, fmaxf(sc[na][2], sc[na][3]));
            }
            rm_lo = fmaxf(rm_lo, __shfl_xor_sync(0xffffffff, rm_lo, 1));
            rm_lo = fmaxf(rm_lo, __shfl_xor_sync(0xffffffff, rm_lo, 2));
            rm_hi = fmaxf(rm_hi, __shfl_xor_sync(0xffffffff, rm_hi, 1));
            rm_hi = fmaxf(rm_hi, __shfl_xor_sync(0xffffffff, rm_hi, 2));

            float mn_lo = fmaxf(m_lo, rm_lo);
            float mn_hi = fmaxf(m_hi, rm_hi);
            float corr_lo = exp2f(m_lo - mn_lo);
            float corr_hi = exp2f(m_hi - mn_hi);
            m_lo = mn_lo; m_hi = mn_hi;

            // exponentiate + pack P straight into a-fragment registers
            uint32_t ppack[16];
            float ps_lo = 0.0f, ps_hi = 0.0f;
#pragma unroll
            for (int na = 0; na < 8; na++) {
                float p0 = exp2f(sc[na][0] - m_lo);
                float p1 = exp2f(sc[na][1] - m_lo);
                float p2 = exp2f(sc[na][2] - m_hi);
                float p3 = exp2f(sc[na][3] - m_hi);
                ps_lo += p0 + p1;
                ps_hi += p2 + p3;
                ppack[2 * na]     = h2(p0, p1);
                ppack[2 * na + 1] = h2(p2, p3);
                acc[na][0] *= corr_lo; acc[na][1] *= corr_lo;
                acc[na][2] *= corr_hi; acc[na][3] *= corr_hi;
            }
            ps_lo += __shfl_xor_sync(0xffffffff, ps_lo, 1);
            ps_lo += __shfl_xor_sync(0xffffffff, ps_lo, 2);
            ps_hi += __shfl_xor_sync(0xffffffff, ps_hi, 1);
            ps_hi += __shfl_xor_sync(0xffffffff, ps_hi, 2);
            l_lo = l_lo * corr_lo + ps_lo;
            l_hi = l_hi * corr_hi + ps_hi;

            // O += P @ V (P direct from registers; V b-frags via ldmatrix.trans)
#pragma unroll
            for (int kc = 0; kc < 4; kc++) {
                uint32_t a0 = ppack[4 * kc];
                uint32_t a1 = ppack[4 * kc + 1];
                uint32_t a2 = ppack[4 * kc + 2];
                uint32_t a3 = ppack[4 * kc + 3];
#pragma unroll
                for (int na2 = 0; na2 < 4; na2++) {
                    uint32_t vd[4];
                    ldsm4t(vd, curV + ((kc * 16 + gh * 8 + r8) * FSTR + na2 * 8 + gv * 4) * 4);
                    mma_f16(acc[2*na2],     a0, a1, a2, a3, vd[0], vd[1]);
                    mma_f16(acc[2*na2 + 1], a0, a1, a2, a3, vd[2], vd[3]);
                }
            }
        }
    }

    float inv_lo = 1.0f / l_lo;
    float inv_hi = 1.0f / l_hi;
    size_t r0 = (size_t)(b * SS + qb + warp * 16 + lr);
    size_t r1 = r0 + 8;
#pragma unroll
    for (int na = 0; na < 8; na++) {
        int wd = na * 4 + lc;
        O[(r0 * NH + h) * 32 + wd] = h2(acc[na][0] * inv_lo, acc[na][1] * inv_lo);
        O[(r1 * NH + h) * 32 + wd] = h2(acc[na][2] * inv_hi, acc[na][3] * inv_hi);
    }
}

// ============================================================
// launch
// ============================================================
extern "C" void kernel_launch(void* const* d_in, const int* in_sizes, int n_in,
                              void* d_out, int out_size)
{
    const float* x  = (const float*)d_in[0];
    const float* Wq = (const float*)d_in[1];
    const float* Wk = (const float*)d_in[2];
    const float* Wv = (const float*)d_in[3];
    const float* Wo = (const float*)d_in[4];
    float* out = (float*)d_out;

    void *q, *k, *v, *ctx, *xh, *wqkvT, *woT;
    cudaGetSymbolAddress(&q,     g_q);
    cudaGetSymbolAddress(&k,     g_k);
    cudaGetSymbolAddress(&v,     g_v);
    cudaGetSymbolAddress(&ctx,   g_ctx);
    cudaGetSymbolAddress(&xh,    g_xh);
    cudaGetSymbolAddress(&wqkvT, g_wqkvT);
    cudaGetSymbolAddress(&woT,   g_woT);

    const int M = BB * SS;  // 8192

    cudaFuncSetAttribute(gemm_h<0>, cudaFuncAttributeMaxDynamicSharedMemorySize, GEMM_SMEM);
    cudaFuncSetAttribute(gemm_h<1>, cudaFuncAttributeMaxDynamicSharedMemorySize, GEMM_SMEM);
    cudaFuncSetAttribute(flash_f16, cudaFuncAttributeMaxDynamicSharedMemorySize, FLASH_SMEM);

    {
        int n4 = M * DD / 4;
        int tot = n4 + SS * 32;
        prep_kernel<<<(tot + 255) / 256, 256>>>((const float4*)x, (uint2*)xh, n4);
    }
    transpose_w<<<dim3(32, 32, 4), dim3(32, 8)>>>(
        Wq, Wk, Wv, Wo, (__half*)wqkvT, (__half*)woT);

    // fused QKV projection + RoPE
    gemm_h<0><<<dim3(12, M / 128), 256, GEMM_SMEM>>>(
        (const uint4*)xh, (const uint4*)wqkvT,
        (uint32_t*)q, (uint32_t*)k, (uint32_t*)v, nullptr, DD, DD / 32);

    // attention
    flash_f16<<<dim3(SS / 128, NH, BB), 256, FLASH_SMEM>>>(
        (const uint4*)q, (const uint4*)k, (const uint4*)v, (uint32_t*)ctx);

    // output projection
    gemm_h<1><<<dim3(8, M / 128), 256, GEMM_SMEM>>>(
        (const uint4*)ctx, (const uint4*)woT,
        nullptr, nullptr, nullptr, out, DD, DD / 32);
}